// round 15
// baseline (speedup 1.0000x reference)
#include <cuda_runtime.h>
#include <cuda_fp16.h>
#include <math.h>
#include <stdint.h>

typedef __half hf;

// ===================== device scratch (no allocation allowed) ==============
__device__ hf g_actA[4096 * 2048];      // L1/L5 out (per row-group)
__device__ hf g_actB[4096 * 1024];      // L2 out (per row-group)
__device__ hf g_actD[4096 * 1024];      // L4 out (per row-group)
__device__ hf g_actC[4096 * 1024];      // branch-2 private activations
__device__ hf g_x1v [4096 * 512];
__device__ hf g_x2v [4096 * 512];
__device__ hf g_wh  [8912896];
__device__ hf g_in  [6291456];
__device__ float g_scores[(size_t)4096 * 4096];
__device__ unsigned g_minkey;
__device__ unsigned g_maxkey;

// weight pool offsets (elements)
#define OW11 0u
#define OW12 2097152u
#define OW13 4194304u
#define OW14 4718592u
#define OW15 5242880u
#define OW21 7340032u
#define OW22 7864320u
#define OW23 8388608u
#define OX1  0u
#define OX2  4194304u

// ===================== PTX helpers =========================================
__device__ __forceinline__ uint32_t smem_to_u32(const void* p) {
    uint32_t a;
    asm("{ .reg .u64 t; cvta.to.shared.u64 t, %1; cvt.u32.u64 %0, t; }"
        : "=r"(a) : "l"(p));
    return a;
}

#define CP_ASYNC16(dst, src) \
    asm volatile("cp.async.cg.shared.global [%0], [%1], 16;" \
                 :: "r"(dst), "l"(src) : "memory")
#define CP_COMMIT() asm volatile("cp.async.commit_group;" ::: "memory")
#define CP_WAIT1()  asm volatile("cp.async.wait_group 1;" ::: "memory")
#define CP_WAIT0()  asm volatile("cp.async.wait_group 0;" ::: "memory")

#define LDSM_X4(r0, r1, r2, r3, addr) \
    asm volatile("ldmatrix.sync.aligned.m8n8.x4.shared.b16 {%0,%1,%2,%3}, [%4];" \
                 : "=r"(r0), "=r"(r1), "=r"(r2), "=r"(r3) : "r"(addr))

__device__ __forceinline__ void mma_f16(float* c, uint32_t a0, uint32_t a1,
                                        uint32_t a2, uint32_t a3,
                                        uint32_t b0, uint32_t b1) {
    asm volatile(
        "mma.sync.aligned.m16n8k16.row.col.f32.f16.f16.f32 "
        "{%0,%1,%2,%3}, {%4,%5,%6,%7}, {%8,%9}, {%0,%1,%2,%3};"
        : "+f"(c[0]), "+f"(c[1]), "+f"(c[2]), "+f"(c[3])
        : "r"(a0), "r"(a1), "r"(a2), "r"(a3), "r"(b0), "r"(b1));
}

// ===================== misc helpers ========================================
__device__ __forceinline__ unsigned f2key(float f) {
    unsigned u = __float_as_uint(f);
    return (u & 0x80000000u) ? ~u : (u | 0x80000000u);
}
__device__ __forceinline__ float key2f(unsigned k) {
    unsigned u = (k & 0x80000000u) ? (k ^ 0x80000000u) : ~k;
    return __uint_as_float(u);
}
enum { ACT_NONE = 0, ACT_RELU = 1, ACT_SIG = 2 };
__device__ __forceinline__ float apply_act(float v, int act) {
    if (act == ACT_RELU) return fmaxf(v, 0.0f);
    if (act == ACT_SIG)  return 1.0f / (1.0f + expf(-v));
    return v;
}

// ===================== fp32 -> fp16 conversion =============================
__global__ void __launch_bounds__(256)
conv_h(const float* __restrict__ in, hf* __restrict__ outp, int n)
{
    int i = (blockIdx.x * 256 + threadIdx.x) * 4;
    if (i >= n) return;
    float4 v = *(const float4*)(in + i);
    __half2 a = __floats2half2_rn(v.x, v.y);
    __half2 b = __floats2half2_rn(v.z, v.w);
    uint2 p;
    p.x = *(uint32_t*)&a; p.y = *(uint32_t*)&b;
    *(uint2*)(outp + i) = p;
}

// ===================== fp16 warp-MMA GEMM ==================================
// C = act(A[M,K] @ B[N,K]^T + bias); A,B fp16, fp32 accumulate.
// BM=BN=128, BK=64. 16 warps (4x4), warp tile 32x32. 3-stage cp.async.
#define ROW_BYTES   144u
#define TIER_BYTES  18432u           // 128 * 144
#define NSTAGE      3
#define GSMEM2      (NSTAGE * 2 * 18432 + 1024)

template <int ACT, bool OUTF>
__global__ void __launch_bounds__(512, 1)
gemm_mma(const hf* __restrict__ A, const hf* __restrict__ Bm,
         const float* __restrict__ bias,
         float* __restrict__ Cf, hf* __restrict__ Ch,
         int M, int N, int K)
{
    constexpr uint32_t STB = 2 * TIER_BYTES;
    extern __shared__ char smem[];
    const uint32_t sb = smem_to_u32(smem);
    const int tid = threadIdx.x;
    const int wid = tid >> 5, lane = tid & 31;
    const int wm = wid & 3, wn = wid >> 2;
    const int bm = blockIdx.y * 128, bn = blockIdx.x * 128;

    float* biasS = (float*)(smem + NSTAGE * STB);
    if (!OUTF && tid < 128) biasS[tid] = bias[bn + tid];

    const int quad = lane >> 3, r8 = lane & 7;
    const uint32_t aoff = (uint32_t)((wm * 32 + (quad & 1) * 8 + r8) * ROW_BYTES
                                     + (quad >> 1) * 16);
    const uint32_t boff = (uint32_t)((wn * 32 + (quad >> 1) * 8 + r8) * ROW_BYTES
                                     + (quad & 1) * 16);

    float acc[2][4][4];
#pragma unroll
    for (int i = 0; i < 2; i++)
#pragma unroll
        for (int j = 0; j < 4; j++)
#pragma unroll
            for (int q = 0; q < 4; q++) acc[i][j][q] = 0.0f;

    const int T = K >> 6;

    auto load_stage = [&](int st, int k0) {
        const uint32_t base = sb + (uint32_t)st * STB;
#pragma unroll
        for (int i = 0; i < 4; i++) {
            int id = tid + i * 512;              // 0..2047
            int tier = id >> 10;
            int rid = id & 1023;
            int row = rid >> 3, c = rid & 7;
            const hf* src = (tier == 0) ? A : Bm;
            int rbase = (tier == 0) ? bm : bn;
            const hf* g = src + (size_t)(rbase + row) * K + k0 + c * 8;
            uint32_t d = base + (uint32_t)tier * TIER_BYTES
                         + (uint32_t)row * ROW_BYTES + (uint32_t)c * 16;
            CP_ASYNC16(d, g);
        }
        CP_COMMIT();
    };

    auto compute_stage = [&](int st) {
        const uint32_t base = sb + (uint32_t)st * STB;
        const uint32_t Ah = base;
        const uint32_t Bh = base + TIER_BYTES;
#pragma unroll
        for (int ks = 0; ks < 4; ks++) {
            const uint32_t ko = (uint32_t)ks * 32;
            uint32_t ah[2][4], bh[2][4];
            LDSM_X4(ah[0][0], ah[0][1], ah[0][2], ah[0][3], Ah + aoff + ko);
            LDSM_X4(ah[1][0], ah[1][1], ah[1][2], ah[1][3], Ah + aoff + 2304 + ko);
            LDSM_X4(bh[0][0], bh[0][1], bh[0][2], bh[0][3], Bh + boff + ko);
            LDSM_X4(bh[1][0], bh[1][1], bh[1][2], bh[1][3], Bh + boff + 2304 + ko);
#pragma unroll
            for (int p = 0; p < 2; p++)
#pragma unroll
                for (int sub = 0; sub < 2; sub++) {
                    int nj = p * 2 + sub;
                    uint32_t h0 = bh[p][sub * 2], h1 = bh[p][sub * 2 + 1];
#pragma unroll
                    for (int mi = 0; mi < 2; mi++)
                        mma_f16(acc[mi][nj], ah[mi][0], ah[mi][1], ah[mi][2], ah[mi][3], h0, h1);
                }
        }
    };

    load_stage(0, 0);
    load_stage(1, 64);
    for (int t = 0; t < T; t++) {
        if (t + 1 < T) CP_WAIT1(); else CP_WAIT0();
        __syncthreads();
        if (t + 2 < T) load_stage((t + 2) % NSTAGE, (t + 2) * 64);
        compute_stage(t % NSTAGE);
    }

    // ---------------- epilogue ----------------
    float lmin = INFINITY, lmax = -INFINITY;
    const int rbase = bm + wm * 32 + (lane >> 2);
    const int cloc0 = wn * 32 + (lane & 3) * 2;
#pragma unroll
    for (int mi = 0; mi < 2; mi++) {
#pragma unroll
        for (int nj = 0; nj < 4; nj++) {
            int cl = cloc0 + nj * 8;
            int n0 = bn + cl;
            float b0 = 0.f, b1 = 0.f;
            if (!OUTF) { b0 = biasS[cl]; b1 = biasS[cl + 1]; }
#pragma unroll
            for (int h = 0; h < 2; h++) {
                int m = rbase + mi * 16 + h * 8;
                float v0 = apply_act(acc[mi][nj][h * 2 + 0] + b0, ACT);
                float v1 = apply_act(acc[mi][nj][h * 2 + 1] + b1, ACT);
                if (OUTF) {
                    lmin = fminf(lmin, fminf(v0, v1));
                    lmax = fmaxf(lmax, fmaxf(v0, v1));
                    *(float2*)(Cf + (size_t)m * N + n0) = make_float2(v0, v1);
                } else {
                    __half2 hv = __floats2half2_rn(v0, v1);
                    *(__half2*)(Ch + (size_t)m * N + n0) = hv;
                }
            }
        }
    }

    if (OUTF) {
        float* red = (float*)smem;
        __syncthreads();
        red[tid] = lmin; red[512 + tid] = lmax;
        __syncthreads();
#pragma unroll
        for (int s = 256; s >= 64; s >>= 1) {
            if (tid < s) {
                red[tid] = fminf(red[tid], red[tid + s]);
                red[512 + tid] = fmaxf(red[512 + tid], red[512 + tid + s]);
            }
            __syncthreads();
        }
        if (tid < 32) {
            float a = fminf(red[tid], red[tid + 32]);
            float b = fmaxf(red[512 + tid], red[512 + tid + 32]);
#pragma unroll
            for (int o = 16; o > 0; o >>= 1) {
                a = fminf(a, __shfl_down_sync(0xffffffffu, a, o));
                b = fmaxf(b, __shfl_down_sync(0xffffffffu, b, o));
            }
            if (tid == 0) {
                atomicMin(&g_minkey, f2key(a));
                atomicMax(&g_maxkey, f2key(b));
            }
        }
    }
}

// ===================== N=1 projection from fp16 activations ================
template <int ACT>
__global__ void __launch_bounds__(256)
rowdot_h(const hf* __restrict__ act, const float* __restrict__ w,
         const float* __restrict__ bias, float* __restrict__ out, int K)
{
    const int warp = threadIdx.x >> 5, lane = threadIdx.x & 31;
    const int row = blockIdx.x * 8 + warp;
    const hf* a = act + (size_t)row * K;
    float s = 0.0f;
    for (int k = lane * 8; k < K; k += 32 * 8) {
        uint4 av = *(const uint4*)(a + k);
        float4 w0 = *(const float4*)(w + k);
        float4 w1 = *(const float4*)(w + k + 4);
        const uint32_t au[4] = {av.x, av.y, av.z, av.w};
        const float wf[8] = {w0.x, w0.y, w0.z, w0.w, w1.x, w1.y, w1.z, w1.w};
#pragma unroll
        for (int q = 0; q < 4; q++) {
            __half2 h2 = *(const __half2*)&au[q];
            s += __low2float(h2) * wf[q * 2];
            s += __high2float(h2) * wf[q * 2 + 1];
        }
    }
#pragma unroll
    for (int o = 16; o > 0; o >>= 1) s += __shfl_down_sync(0xffffffffu, s, o);
    if (lane == 0) out[row] = apply_act(s + bias[0], ACT);
}

// ===================== min/max init + final rescale ========================
__global__ void init_minmax_k() { g_minkey = 0xFFFFFFFFu; g_maxkey = 0u; }

__global__ void __launch_bounds__(256)
scale_out(const float* __restrict__ s, float* __restrict__ out)
{
    float mn = key2f(g_minkey);
    float mx = key2f(g_maxkey);
    float inv = 1.0f / (mx - mn);
    size_t i = ((size_t)blockIdx.x * blockDim.x + threadIdx.x) * 4;
    float4 v = *(const float4*)&s[i];
    float4 o;
    o.x = (v.x - mn) * inv; o.y = (v.y - mn) * inv;
    o.z = (v.z - mn) * inv; o.w = (v.w - mn) * inv;
    *(float4*)&out[i] = o;
}

// ===================== host launch =========================================
static void launch_layer(cudaStream_t st, int act, const hf* A, const hf* W,
                         const float* bias, hf* C, int M, int N, int K)
{
    dim3 grid(N / 128, M / 128), blk(512);
    if (act == ACT_RELU) {
        cudaFuncSetAttribute(gemm_mma<ACT_RELU, false>,
                             cudaFuncAttributeMaxDynamicSharedMemorySize, GSMEM2);
        gemm_mma<ACT_RELU, false><<<grid, blk, GSMEM2, st>>>(
            A, W, bias, nullptr, C, M, N, K);
    } else {
        cudaFuncSetAttribute(gemm_mma<ACT_SIG, false>,
                             cudaFuncAttributeMaxDynamicSharedMemorySize, GSMEM2);
        gemm_mma<ACT_SIG, false><<<grid, blk, GSMEM2, st>>>(
            A, W, bias, nullptr, C, M, N, K);
    }
}

extern "C" void kernel_launch(void* const* d_in, const int* in_sizes, int n_in,
                              void* d_out, int out_size)
{
    (void)in_sizes; (void)n_in; (void)out_size;
    const float* x1   = (const float*)d_in[0];
    const float* x2   = (const float*)d_in[1];
    const float* W1_1 = (const float*)d_in[2];   const float* b1_1 = (const float*)d_in[3];
    const float* W1_2 = (const float*)d_in[4];   const float* b1_2 = (const float*)d_in[5];
    const float* W1_3 = (const float*)d_in[6];   const float* b1_3 = (const float*)d_in[7];
    const float* W1_4 = (const float*)d_in[8];   const float* b1_4 = (const float*)d_in[9];
    const float* W1_5 = (const float*)d_in[10];  const float* b1_5 = (const float*)d_in[11];
    const float* Wp1  = (const float*)d_in[12];  const float* bp1  = (const float*)d_in[13];
    const float* W2_1 = (const float*)d_in[14];  const float* b2_1 = (const float*)d_in[15];
    const float* W2_2 = (const float*)d_in[16];  const float* b2_2 = (const float*)d_in[17];
    const float* W2_3 = (const float*)d_in[18];  const float* b2_3 = (const float*)d_in[19];
    const float* Wp2  = (const float*)d_in[20];  const float* bp2  = (const float*)d_in[21];

    float* out = (float*)d_out;
    const int B = 4096;
    const int H = 1024;                  // row-group size (B/4)
    const size_t NSC = (size_t)4096 * 4096;

    hf *actA, *actB, *actD, *actC, *x1v, *x2v, *wh, *inp;
    float* scores;
    cudaGetSymbolAddress((void**)&actA, g_actA);
    cudaGetSymbolAddress((void**)&actB, g_actB);
    cudaGetSymbolAddress((void**)&actD, g_actD);
    cudaGetSymbolAddress((void**)&actC, g_actC);
    cudaGetSymbolAddress((void**)&x1v, g_x1v);
    cudaGetSymbolAddress((void**)&x2v, g_x2v);
    cudaGetSymbolAddress((void**)&wh, g_wh);
    cudaGetSymbolAddress((void**)&inp, g_in);
    cudaGetSymbolAddress((void**)&scores, g_scores);

    // streams/events created once (host-side only; no device allocation)
    // Exactly 4 streams (0, s2, s3, s4) — 5 streams trips the teardown check.
    static cudaStream_t s2 = nullptr, s3 = nullptr, s4 = nullptr;
    static cudaEvent_t evFork = nullptr, evX2v = nullptr, evS3 = nullptr,
                       evW1r = nullptr, evW11 = nullptr, evX1c = nullptr,
                       evE2 = nullptr, evE4 = nullptr;
    static cudaEvent_t evX1vq[4] = {nullptr, nullptr, nullptr, nullptr};
    if (!s2) {
        cudaStreamCreateWithFlags(&s2, cudaStreamNonBlocking);
        cudaStreamCreateWithFlags(&s3, cudaStreamNonBlocking);
        cudaStreamCreateWithFlags(&s4, cudaStreamNonBlocking);
        cudaEventCreateWithFlags(&evFork, cudaEventDisableTiming);
        cudaEventCreateWithFlags(&evX2v,  cudaEventDisableTiming);
        cudaEventCreateWithFlags(&evS3,   cudaEventDisableTiming);
        cudaEventCreateWithFlags(&evW1r,  cudaEventDisableTiming);
        cudaEventCreateWithFlags(&evW11,  cudaEventDisableTiming);
        cudaEventCreateWithFlags(&evX1c,  cudaEventDisableTiming);
        cudaEventCreateWithFlags(&evE2,   cudaEventDisableTiming);
        cudaEventCreateWithFlags(&evE4,   cudaEventDisableTiming);
        for (int q = 0; q < 4; q++)
            cudaEventCreateWithFlags(&evX1vq[q], cudaEventDisableTiming);
    }

    // ---- stream0: init + fork ----
    init_minmax_k<<<1, 1>>>();
    cudaEventRecord(evFork, 0);
    cudaStreamWaitEvent(s2, evFork, 0);
    cudaStreamWaitEvent(s3, evFork, 0);
    cudaStreamWaitEvent(s4, evFork, 0);

    // ---- s4: W1 weight convs, then group-1 pipeline ----
    conv_h<<<2097152 / 1024, 256, 0, s4>>>(W1_1, wh + OW11, 2097152);
    cudaEventRecord(evW11, s4);
    conv_h<<<2097152 / 1024, 256, 0, s4>>>(W1_2, wh + OW12, 2097152);
    conv_h<<<524288 / 1024, 256, 0, s4>>>(W1_3, wh + OW13, 524288);
    conv_h<<<524288 / 1024, 256, 0, s4>>>(W1_4, wh + OW14, 524288);
    conv_h<<<2097152 / 1024, 256, 0, s4>>>(W1_5, wh + OW15, 2097152);
    cudaEventRecord(evW1r, s4);

    // ---- s2: branch 2 (then group-2 pipeline) ----
    conv_h<<<2097152 / 1024, 256, 0, s2>>>(x2, inp + OX2, 2097152);
    conv_h<<<524288 / 1024, 256, 0, s2>>>(W2_1, wh + OW21, 524288);
    conv_h<<<524288 / 1024, 256, 0, s2>>>(W2_2, wh + OW22, 524288);
    conv_h<<<524288 / 1024, 256, 0, s2>>>(W2_3, wh + OW23, 524288);
    launch_layer(s2, ACT_RELU, inp + OX2, wh + OW21, b2_1, actC, B, 1024, 512);
    launch_layer(s2, ACT_SIG,  actC, wh + OW22, b2_2, x2v, B, 512, 1024);
    cudaEventRecord(evX2v, s2);
    launch_layer(s2, ACT_RELU, x2v, wh + OW23, b2_3, actC, B, 1024, 512);
    rowdot_h<ACT_SIG><<<B / 8, 256, 0, s2>>>(actC, Wp2, bp2, out + 4096 + NSC, 1024); // pre_model

    // ---- stream0: x1 conversion (parallel with W1 convs on s4) ----
    conv_h<<<4194304 / 1024, 256>>>(x1, inp + OX1, 4194304);
    cudaEventRecord(evX1c, 0);

    // ---- branch 1 as four independent 1024-row pipelines ----
    // g0 -> stream0, g1 -> s4, g2 -> s2 (after branch 2), g3 -> s3.
    // Per-group disjoint buffer regions (H = 1024):
    //   L1 out: actA + g*H*2048   L2 out: actB + g*H*1024
    //   L3 out: x1v + g*H*512     L4 out: actD + g*H*1024
    //   L5 out: actA + g*H*2048 (reuse own L1 region; own L2 already consumed)
    cudaStreamWaitEvent(0,  evW11, 0);                  // g0: L1 weights ready
    cudaStreamWaitEvent(s4, evX1c, 0);                  // g1: input ready (weights in-stream)
    cudaStreamWaitEvent(s2, evX1c, 0);                  // g2
    cudaStreamWaitEvent(s2, evW1r, 0);
    cudaStreamWaitEvent(s3, evX1c, 0);                  // g3
    cudaStreamWaitEvent(s3, evW11, 0);

    for (int g = 0; g < 4; g++) {
        cudaStream_t sg = (g == 0) ? (cudaStream_t)0
                        : (g == 1) ? s4
                        : (g == 2) ? s2 : s3;
        const hf* xin = inp + OX1 + (size_t)g * H * 1024;
        hf* a1 = actA + (size_t)g * H * 2048;
        hf* a2 = actB + (size_t)g * H * 1024;
        hf* xv = x1v  + (size_t)g * H * 512;
        hf* a4 = actD + (size_t)g * H * 1024;
        hf* a5 = actA + (size_t)g * H * 2048;

        launch_layer(sg, ACT_RELU, xin, wh + OW11, b1_1, a1, H, 2048, 1024);
        if (g == 0 || g == 3) cudaStreamWaitEvent(sg, evW1r, 0);  // s4/s2 have it in-stream
        launch_layer(sg, ACT_RELU, a1, wh + OW12, b1_2, a2, H, 1024, 2048);
        launch_layer(sg, ACT_SIG,  a2, wh + OW13, b1_3, xv, H, 512, 1024);
        cudaEventRecord(evX1vq[g], sg);
        launch_layer(sg, ACT_RELU, xv, wh + OW14, b1_4, a4, H, 1024, 512);
        launch_layer(sg, ACT_RELU, a4, wh + OW15, b1_5, a5, H, 2048, 1024);
        rowdot_h<ACT_SIG><<<H / 8, 256, 0, sg>>>(a5, Wp1, bp1,
                                                 out + (size_t)g * H, 2048); // pre_data
    }
    cudaEventRecord(evE2, s2);
    cudaEventRecord(evE4, s4);

    // ---- s3 (after g3 pipeline): scores quarters + rescale ----
    cudaStreamWaitEvent(s3, evX2v, 0);
    cudaFuncSetAttribute(gemm_mma<ACT_NONE, true>,
                         cudaFuncAttributeMaxDynamicSharedMemorySize, GSMEM2);
    for (int q = 0; q < 4; q++) {
        cudaStreamWaitEvent(s3, evX1vq[q], 0);
        dim3 grid(4096 / 128, H / 128), blk(512);
        gemm_mma<ACT_NONE, true><<<grid, blk, GSMEM2, s3>>>(
            x1v + (size_t)q * H * 512, x2v, nullptr,
            scores + (size_t)q * H * 4096, nullptr, H, 4096, 512);
    }
    scale_out<<<(unsigned)(NSC / 4 / 256), 256, 0, s3>>>(scores, out + 4096);     // pre_dm
    cudaEventRecord(evS3, s3);

    // ---- join everything back into stream0 ----
    cudaStreamWaitEvent(0, evE2, 0);
    cudaStreamWaitEvent(0, evE4, 0);
    cudaStreamWaitEvent(0, evS3, 0);
}

// round 16
// speedup vs baseline: 1.0469x; 1.0469x over previous
#include <cuda_runtime.h>
#include <cuda_fp16.h>
#include <math.h>
#include <stdint.h>

typedef __half hf;

// ===================== device scratch (no allocation allowed) ==============
__device__ hf g_actA[4096 * 2048];      // L1/L5 out (per row-group)
__device__ hf g_actB[4096 * 1024];      // L2 out (per row-group)
__device__ hf g_actD[4096 * 1024];      // L4 out (per row-group)
__device__ hf g_actC[4096 * 1024];      // branch-2 private activations
__device__ hf g_x1v [4096 * 512];
__device__ hf g_x2v [4096 * 512];
__device__ hf g_wh  [8912896];
__device__ hf g_in  [6291456];
__device__ float g_scores[(size_t)4096 * 4096];
__device__ unsigned g_minkey;
__device__ unsigned g_maxkey;

// weight pool offsets (elements)
#define OW11 0u
#define OW12 2097152u
#define OW13 4194304u
#define OW14 4718592u
#define OW15 5242880u
#define OW21 7340032u
#define OW22 7864320u
#define OW23 8388608u
#define OX1  0u
#define OX2  4194304u

// ===================== PTX helpers =========================================
__device__ __forceinline__ uint32_t smem_to_u32(const void* p) {
    uint32_t a;
    asm("{ .reg .u64 t; cvta.to.shared.u64 t, %1; cvt.u32.u64 %0, t; }"
        : "=r"(a) : "l"(p));
    return a;
}

#define CP_ASYNC16(dst, src) \
    asm volatile("cp.async.cg.shared.global [%0], [%1], 16;" \
                 :: "r"(dst), "l"(src) : "memory")
#define CP_COMMIT() asm volatile("cp.async.commit_group;" ::: "memory")
#define CP_WAIT1()  asm volatile("cp.async.wait_group 1;" ::: "memory")
#define CP_WAIT0()  asm volatile("cp.async.wait_group 0;" ::: "memory")

#define LDSM_X4(r0, r1, r2, r3, addr) \
    asm volatile("ldmatrix.sync.aligned.m8n8.x4.shared.b16 {%0,%1,%2,%3}, [%4];" \
                 : "=r"(r0), "=r"(r1), "=r"(r2), "=r"(r3) : "r"(addr))

__device__ __forceinline__ void mma_f16(float* c, uint32_t a0, uint32_t a1,
                                        uint32_t a2, uint32_t a3,
                                        uint32_t b0, uint32_t b1) {
    asm volatile(
        "mma.sync.aligned.m16n8k16.row.col.f32.f16.f16.f32 "
        "{%0,%1,%2,%3}, {%4,%5,%6,%7}, {%8,%9}, {%0,%1,%2,%3};"
        : "+f"(c[0]), "+f"(c[1]), "+f"(c[2]), "+f"(c[3])
        : "r"(a0), "r"(a1), "r"(a2), "r"(a3), "r"(b0), "r"(b1));
}

// ===================== misc helpers ========================================
__device__ __forceinline__ unsigned f2key(float f) {
    unsigned u = __float_as_uint(f);
    return (u & 0x80000000u) ? ~u : (u | 0x80000000u);
}
__device__ __forceinline__ float key2f(unsigned k) {
    unsigned u = (k & 0x80000000u) ? (k ^ 0x80000000u) : ~k;
    return __uint_as_float(u);
}
enum { ACT_NONE = 0, ACT_RELU = 1, ACT_SIG = 2 };
__device__ __forceinline__ float apply_act(float v, int act) {
    if (act == ACT_RELU) return fmaxf(v, 0.0f);
    if (act == ACT_SIG)  return 1.0f / (1.0f + expf(-v));
    return v;
}

// ===================== fp32 -> fp16 conversion =============================
__global__ void __launch_bounds__(256)
conv_h(const float* __restrict__ in, hf* __restrict__ outp, int n)
{
    int i = (blockIdx.x * 256 + threadIdx.x) * 4;
    if (i >= n) return;
    float4 v = *(const float4*)(in + i);
    __half2 a = __floats2half2_rn(v.x, v.y);
    __half2 b = __floats2half2_rn(v.z, v.w);
    uint2 p;
    p.x = *(uint32_t*)&a; p.y = *(uint32_t*)&b;
    *(uint2*)(outp + i) = p;
}

// ===================== fp16 warp-MMA GEMM ==================================
// C = act(A[M,K] @ B[N,K]^T + bias); A,B fp16, fp32 accumulate.
// BM=BN=128, BK=64. 16 warps (4x4), warp tile 32x32. 3-stage cp.async.
#define ROW_BYTES   144u
#define TIER_BYTES  18432u           // 128 * 144
#define NSTAGE      3
#define GSMEM2      (NSTAGE * 2 * 18432 + 1024)

template <int ACT, bool OUTF>
__global__ void __launch_bounds__(512, 1)
gemm_mma(const hf* __restrict__ A, const hf* __restrict__ Bm,
         const float* __restrict__ bias,
         float* __restrict__ Cf, hf* __restrict__ Ch,
         int M, int N, int K)
{
    constexpr uint32_t STB = 2 * TIER_BYTES;
    extern __shared__ char smem[];
    const uint32_t sb = smem_to_u32(smem);
    const int tid = threadIdx.x;
    const int wid = tid >> 5, lane = tid & 31;
    const int wm = wid & 3, wn = wid >> 2;
    const int bm = blockIdx.y * 128, bn = blockIdx.x * 128;

    float* biasS = (float*)(smem + NSTAGE * STB);
    if (!OUTF && tid < 128) biasS[tid] = bias[bn + tid];

    const int quad = lane >> 3, r8 = lane & 7;
    const uint32_t aoff = (uint32_t)((wm * 32 + (quad & 1) * 8 + r8) * ROW_BYTES
                                     + (quad >> 1) * 16);
    const uint32_t boff = (uint32_t)((wn * 32 + (quad >> 1) * 8 + r8) * ROW_BYTES
                                     + (quad & 1) * 16);

    float acc[2][4][4];
#pragma unroll
    for (int i = 0; i < 2; i++)
#pragma unroll
        for (int j = 0; j < 4; j++)
#pragma unroll
            for (int q = 0; q < 4; q++) acc[i][j][q] = 0.0f;

    const int T = K >> 6;

    auto load_stage = [&](int st, int k0) {
        const uint32_t base = sb + (uint32_t)st * STB;
#pragma unroll
        for (int i = 0; i < 4; i++) {
            int id = tid + i * 512;              // 0..2047
            int tier = id >> 10;
            int rid = id & 1023;
            int row = rid >> 3, c = rid & 7;
            const hf* src = (tier == 0) ? A : Bm;
            int rbase = (tier == 0) ? bm : bn;
            const hf* g = src + (size_t)(rbase + row) * K + k0 + c * 8;
            uint32_t d = base + (uint32_t)tier * TIER_BYTES
                         + (uint32_t)row * ROW_BYTES + (uint32_t)c * 16;
            CP_ASYNC16(d, g);
        }
        CP_COMMIT();
    };

    auto compute_stage = [&](int st) {
        const uint32_t base = sb + (uint32_t)st * STB;
        const uint32_t Ah = base;
        const uint32_t Bh = base + TIER_BYTES;
#pragma unroll
        for (int ks = 0; ks < 4; ks++) {
            const uint32_t ko = (uint32_t)ks * 32;
            uint32_t ah[2][4], bh[2][4];
            LDSM_X4(ah[0][0], ah[0][1], ah[0][2], ah[0][3], Ah + aoff + ko);
            LDSM_X4(ah[1][0], ah[1][1], ah[1][2], ah[1][3], Ah + aoff + 2304 + ko);
            LDSM_X4(bh[0][0], bh[0][1], bh[0][2], bh[0][3], Bh + boff + ko);
            LDSM_X4(bh[1][0], bh[1][1], bh[1][2], bh[1][3], Bh + boff + 2304 + ko);
#pragma unroll
            for (int p = 0; p < 2; p++)
#pragma unroll
                for (int sub = 0; sub < 2; sub++) {
                    int nj = p * 2 + sub;
                    uint32_t h0 = bh[p][sub * 2], h1 = bh[p][sub * 2 + 1];
#pragma unroll
                    for (int mi = 0; mi < 2; mi++)
                        mma_f16(acc[mi][nj], ah[mi][0], ah[mi][1], ah[mi][2], ah[mi][3], h0, h1);
                }
        }
    };

    load_stage(0, 0);
    load_stage(1, 64);
    for (int t = 0; t < T; t++) {
        if (t + 1 < T) CP_WAIT1(); else CP_WAIT0();
        __syncthreads();
        if (t + 2 < T) load_stage((t + 2) % NSTAGE, (t + 2) * 64);
        compute_stage(t % NSTAGE);
    }

    // ---------------- epilogue ----------------
    float lmin = INFINITY, lmax = -INFINITY;
    const int rbase = bm + wm * 32 + (lane >> 2);
    const int cloc0 = wn * 32 + (lane & 3) * 2;
#pragma unroll
    for (int mi = 0; mi < 2; mi++) {
#pragma unroll
        for (int nj = 0; nj < 4; nj++) {
            int cl = cloc0 + nj * 8;
            int n0 = bn + cl;
            float b0 = 0.f, b1 = 0.f;
            if (!OUTF) { b0 = biasS[cl]; b1 = biasS[cl + 1]; }
#pragma unroll
            for (int h = 0; h < 2; h++) {
                int m = rbase + mi * 16 + h * 8;
                float v0 = apply_act(acc[mi][nj][h * 2 + 0] + b0, ACT);
                float v1 = apply_act(acc[mi][nj][h * 2 + 1] + b1, ACT);
                if (OUTF) {
                    lmin = fminf(lmin, fminf(v0, v1));
                    lmax = fmaxf(lmax, fmaxf(v0, v1));
                    *(float2*)(Cf + (size_t)m * N + n0) = make_float2(v0, v1);
                } else {
                    __half2 hv = __floats2half2_rn(v0, v1);
                    *(__half2*)(Ch + (size_t)m * N + n0) = hv;
                }
            }
        }
    }

    if (OUTF) {
        float* red = (float*)smem;
        __syncthreads();
        red[tid] = lmin; red[512 + tid] = lmax;
        __syncthreads();
#pragma unroll
        for (int s = 256; s >= 64; s >>= 1) {
            if (tid < s) {
                red[tid] = fminf(red[tid], red[tid + s]);
                red[512 + tid] = fmaxf(red[512 + tid], red[512 + tid + s]);
            }
            __syncthreads();
        }
        if (tid < 32) {
            float a = fminf(red[tid], red[tid + 32]);
            float b = fmaxf(red[512 + tid], red[512 + tid + 32]);
#pragma unroll
            for (int o = 16; o > 0; o >>= 1) {
                a = fminf(a, __shfl_down_sync(0xffffffffu, a, o));
                b = fmaxf(b, __shfl_down_sync(0xffffffffu, b, o));
            }
            if (tid == 0) {
                atomicMin(&g_minkey, f2key(a));
                atomicMax(&g_maxkey, f2key(b));
            }
        }
    }
}

// ===================== N=1 projection from fp16 activations ================
template <int ACT>
__global__ void __launch_bounds__(256)
rowdot_h(const hf* __restrict__ act, const float* __restrict__ w,
         const float* __restrict__ bias, float* __restrict__ out, int K)
{
    const int warp = threadIdx.x >> 5, lane = threadIdx.x & 31;
    const int row = blockIdx.x * 8 + warp;
    const hf* a = act + (size_t)row * K;
    float s = 0.0f;
    for (int k = lane * 8; k < K; k += 32 * 8) {
        uint4 av = *(const uint4*)(a + k);
        float4 w0 = *(const float4*)(w + k);
        float4 w1 = *(const float4*)(w + k + 4);
        const uint32_t au[4] = {av.x, av.y, av.z, av.w};
        const float wf[8] = {w0.x, w0.y, w0.z, w0.w, w1.x, w1.y, w1.z, w1.w};
#pragma unroll
        for (int q = 0; q < 4; q++) {
            __half2 h2 = *(const __half2*)&au[q];
            s += __low2float(h2) * wf[q * 2];
            s += __high2float(h2) * wf[q * 2 + 1];
        }
    }
#pragma unroll
    for (int o = 16; o > 0; o >>= 1) s += __shfl_down_sync(0xffffffffu, s, o);
    if (lane == 0) out[row] = apply_act(s + bias[0], ACT);
}

// ===================== min/max init + final rescale ========================
__global__ void init_minmax_k() { g_minkey = 0xFFFFFFFFu; g_maxkey = 0u; }

__global__ void __launch_bounds__(256)
scale_out(const float* __restrict__ s, float* __restrict__ out)
{
    float mn = key2f(g_minkey);
    float mx = key2f(g_maxkey);
    float inv = 1.0f / (mx - mn);
    size_t i = ((size_t)blockIdx.x * blockDim.x + threadIdx.x) * 4;
    float4 v = *(const float4*)&s[i];
    float4 o;
    o.x = (v.x - mn) * inv; o.y = (v.y - mn) * inv;
    o.z = (v.z - mn) * inv; o.w = (v.w - mn) * inv;
    *(float4*)&out[i] = o;
}

// ===================== host launch =========================================
static void launch_layer(cudaStream_t st, int act, const hf* A, const hf* W,
                         const float* bias, hf* C, int M, int N, int K)
{
    dim3 grid(N / 128, M / 128), blk(512);
    if (act == ACT_RELU) {
        cudaFuncSetAttribute(gemm_mma<ACT_RELU, false>,
                             cudaFuncAttributeMaxDynamicSharedMemorySize, GSMEM2);
        gemm_mma<ACT_RELU, false><<<grid, blk, GSMEM2, st>>>(
            A, W, bias, nullptr, C, M, N, K);
    } else {
        cudaFuncSetAttribute(gemm_mma<ACT_SIG, false>,
                             cudaFuncAttributeMaxDynamicSharedMemorySize, GSMEM2);
        gemm_mma<ACT_SIG, false><<<grid, blk, GSMEM2, st>>>(
            A, W, bias, nullptr, C, M, N, K);
    }
}

extern "C" void kernel_launch(void* const* d_in, const int* in_sizes, int n_in,
                              void* d_out, int out_size)
{
    (void)in_sizes; (void)n_in; (void)out_size;
    const float* x1   = (const float*)d_in[0];
    const float* x2   = (const float*)d_in[1];
    const float* W1_1 = (const float*)d_in[2];   const float* b1_1 = (const float*)d_in[3];
    const float* W1_2 = (const float*)d_in[4];   const float* b1_2 = (const float*)d_in[5];
    const float* W1_3 = (const float*)d_in[6];   const float* b1_3 = (const float*)d_in[7];
    const float* W1_4 = (const float*)d_in[8];   const float* b1_4 = (const float*)d_in[9];
    const float* W1_5 = (const float*)d_in[10];  const float* b1_5 = (const float*)d_in[11];
    const float* Wp1  = (const float*)d_in[12];  const float* bp1  = (const float*)d_in[13];
    const float* W2_1 = (const float*)d_in[14];  const float* b2_1 = (const float*)d_in[15];
    const float* W2_2 = (const float*)d_in[16];  const float* b2_2 = (const float*)d_in[17];
    const float* W2_3 = (const float*)d_in[18];  const float* b2_3 = (const float*)d_in[19];
    const float* Wp2  = (const float*)d_in[20];  const float* bp2  = (const float*)d_in[21];

    float* out = (float*)d_out;
    const int B = 4096;
    const int H = 2048;                  // row-group size (B/2)
    const size_t NSC = (size_t)4096 * 4096;

    hf *actA, *actB, *actD, *actC, *x1v, *x2v, *wh, *inp;
    float* scores;
    cudaGetSymbolAddress((void**)&actA, g_actA);
    cudaGetSymbolAddress((void**)&actB, g_actB);
    cudaGetSymbolAddress((void**)&actD, g_actD);
    cudaGetSymbolAddress((void**)&actC, g_actC);
    cudaGetSymbolAddress((void**)&x1v, g_x1v);
    cudaGetSymbolAddress((void**)&x2v, g_x2v);
    cudaGetSymbolAddress((void**)&wh, g_wh);
    cudaGetSymbolAddress((void**)&inp, g_in);
    cudaGetSymbolAddress((void**)&scores, g_scores);

    // streams/events created once (host-side only; no device allocation)
    // Exactly 4 streams (0, s2, s3, s4) — 5 streams trips the teardown check.
    static cudaStream_t s2 = nullptr, s3 = nullptr, s4 = nullptr;
    static cudaEvent_t evFork = nullptr, evX1v0 = nullptr, evX1v1 = nullptr,
                       evX2v = nullptr, evB2 = nullptr, evS3 = nullptr,
                       evW1r = nullptr, evW11 = nullptr, evX1c = nullptr,
                       evG1 = nullptr;
    if (!s2) {
        cudaStreamCreateWithFlags(&s2, cudaStreamNonBlocking);
        cudaStreamCreateWithFlags(&s3, cudaStreamNonBlocking);
        cudaStreamCreateWithFlags(&s4, cudaStreamNonBlocking);
        cudaEventCreateWithFlags(&evFork, cudaEventDisableTiming);
        cudaEventCreateWithFlags(&evX1v0, cudaEventDisableTiming);
        cudaEventCreateWithFlags(&evX1v1, cudaEventDisableTiming);
        cudaEventCreateWithFlags(&evX2v,  cudaEventDisableTiming);
        cudaEventCreateWithFlags(&evB2,   cudaEventDisableTiming);
        cudaEventCreateWithFlags(&evS3,   cudaEventDisableTiming);
        cudaEventCreateWithFlags(&evW1r,  cudaEventDisableTiming);
        cudaEventCreateWithFlags(&evW11,  cudaEventDisableTiming);
        cudaEventCreateWithFlags(&evX1c,  cudaEventDisableTiming);
        cudaEventCreateWithFlags(&evG1,   cudaEventDisableTiming);
    }

    // ---- stream0: init + fork ----
    init_minmax_k<<<1, 1>>>();
    cudaEventRecord(evFork, 0);
    cudaStreamWaitEvent(s2, evFork, 0);
    cudaStreamWaitEvent(s3, evFork, 0);
    cudaStreamWaitEvent(s4, evFork, 0);

    // ---- s4: W1_1 conv only, then group-1 pipeline ----
    conv_h<<<2097152 / 1024, 256, 0, s4>>>(W1_1, wh + OW11, 2097152);
    cudaEventRecord(evW11, s4);

    // ---- s3: W1_2..W1_5 convs (s3 is otherwise idle until scores) ----
    conv_h<<<2097152 / 1024, 256, 0, s3>>>(W1_2, wh + OW12, 2097152);
    conv_h<<<524288 / 1024, 256, 0, s3>>>(W1_3, wh + OW13, 524288);
    conv_h<<<524288 / 1024, 256, 0, s3>>>(W1_4, wh + OW14, 524288);
    conv_h<<<2097152 / 1024, 256, 0, s3>>>(W1_5, wh + OW15, 2097152);
    cudaEventRecord(evW1r, s3);

    // ---- s2: branch 2 (independent of branch 1) ----
    conv_h<<<2097152 / 1024, 256, 0, s2>>>(x2, inp + OX2, 2097152);
    conv_h<<<524288 / 1024, 256, 0, s2>>>(W2_1, wh + OW21, 524288);
    conv_h<<<524288 / 1024, 256, 0, s2>>>(W2_2, wh + OW22, 524288);
    conv_h<<<524288 / 1024, 256, 0, s2>>>(W2_3, wh + OW23, 524288);
    launch_layer(s2, ACT_RELU, inp + OX2, wh + OW21, b2_1, actC, B, 1024, 512);
    launch_layer(s2, ACT_SIG,  actC, wh + OW22, b2_2, x2v, B, 512, 1024);
    cudaEventRecord(evX2v, s2);
    launch_layer(s2, ACT_RELU, x2v, wh + OW23, b2_3, actC, B, 1024, 512);
    rowdot_h<ACT_SIG><<<B / 8, 256, 0, s2>>>(actC, Wp2, bp2, out + 4096 + NSC, 1024); // pre_model
    cudaEventRecord(evB2, s2);

    // ---- stream0: x1 conversion (parallel with weight convs) ----
    conv_h<<<4194304 / 1024, 256>>>(x1, inp + OX1, 4194304);
    cudaEventRecord(evX1c, 0);

    // ---- branch 1 as two independent 2048-row pipelines ----
    // group 0 on stream0, group 1 on s4. Disjoint buffer regions per group:
    //   L1 out: actA + g*H*2048   L2 out: actB + g*H*1024
    //   L3 out: x1v + g*H*512     L4 out: actD + g*H*1024
    //   L5 out: actA + g*H*2048 (reuse own L1 region; own L2 already consumed)
    cudaStreamWaitEvent(0, evW11, 0);
    cudaStreamWaitEvent(s4, evX1c, 0);

    for (int g = 0; g < 2; g++) {
        cudaStream_t sg = (g == 0) ? (cudaStream_t)0 : s4;
        const hf* xin = inp + OX1 + (size_t)g * H * 1024;
        hf* a1 = actA + (size_t)g * H * 2048;
        hf* a2 = actB + (size_t)g * H * 1024;
        hf* xv = x1v  + (size_t)g * H * 512;
        hf* a4 = actD + (size_t)g * H * 1024;
        hf* a5 = actA + (size_t)g * H * 2048;

        launch_layer(sg, ACT_RELU, xin, wh + OW11, b1_1, a1, H, 2048, 1024);
        cudaStreamWaitEvent(sg, evW1r, 0);   // W1_2..W1_5 converted during L1
        launch_layer(sg, ACT_RELU, a1, wh + OW12, b1_2, a2, H, 1024, 2048);
        launch_layer(sg, ACT_SIG,  a2, wh + OW13, b1_3, xv, H, 512, 1024);
        cudaEventRecord(g == 0 ? evX1v0 : evX1v1, sg);
        launch_layer(sg, ACT_RELU, xv, wh + OW14, b1_4, a4, H, 1024, 512);
        launch_layer(sg, ACT_RELU, a4, wh + OW15, b1_5, a5, H, 2048, 1024);
        rowdot_h<ACT_SIG><<<H / 8, 256, 0, sg>>>(a5, Wp1, bp1,
                                                 out + (size_t)g * H, 2048); // pre_data
    }
    cudaEventRecord(evG1, s4);

    // ---- s3: cross scores (two M-halves) + rescale ----
    cudaStreamWaitEvent(s3, evX2v, 0);
    cudaFuncSetAttribute(gemm_mma<ACT_NONE, true>,
                         cudaFuncAttributeMaxDynamicSharedMemorySize, GSMEM2);
    for (int g = 0; g < 2; g++) {
        cudaStreamWaitEvent(s3, g == 0 ? evX1v0 : evX1v1, 0);
        dim3 grid(4096 / 128, H / 128), blk(512);
        gemm_mma<ACT_NONE, true><<<grid, blk, GSMEM2, s3>>>(
            x1v + (size_t)g * H * 512, x2v, nullptr,
            scores + (size_t)g * H * 4096, nullptr, H, 4096, 512);
    }
    scale_out<<<(unsigned)(NSC / 4 / 256), 256, 0, s3>>>(scores, out + 4096);     // pre_dm
    cudaEventRecord(evS3, s3);

    // ---- join everything back into stream0 ----
    cudaStreamWaitEvent(0, evB2, 0);
    cudaStreamWaitEvent(0, evS3, 0);
    cudaStreamWaitEvent(0, evG1, 0);
}

// round 17
// speedup vs baseline: 1.0645x; 1.0168x over previous
#include <cuda_runtime.h>
#include <cuda_fp16.h>
#include <math.h>
#include <stdint.h>

typedef __half hf;

// ===================== device scratch (no allocation allowed) ==============
__device__ hf g_actA[4096 * 2048];      // L1/L5 out (per row-group)
__device__ hf g_actB[4096 * 1024];      // L2 out (per row-group)
__device__ hf g_actD[4096 * 1024];      // L4 out (per row-group)
__device__ hf g_actC[4096 * 1024];      // branch-2 private activations
__device__ hf g_x1v [4096 * 512];
__device__ hf g_x2v [4096 * 512];
__device__ hf g_wh  [8912896];
__device__ hf g_in  [6291456];
__device__ float g_scores[(size_t)4096 * 4096];
__device__ unsigned g_minkey;
__device__ unsigned g_maxkey;

// weight pool offsets (elements)
#define OW11 0u
#define OW12 2097152u
#define OW13 4194304u
#define OW14 4718592u
#define OW15 5242880u
#define OW21 7340032u
#define OW22 7864320u
#define OW23 8388608u
#define OX1  0u
#define OX2  4194304u

// ===================== PTX helpers =========================================
__device__ __forceinline__ uint32_t smem_to_u32(const void* p) {
    uint32_t a;
    asm("{ .reg .u64 t; cvta.to.shared.u64 t, %1; cvt.u32.u64 %0, t; }"
        : "=r"(a) : "l"(p));
    return a;
}

#define CP_ASYNC16(dst, src) \
    asm volatile("cp.async.cg.shared.global [%0], [%1], 16;" \
                 :: "r"(dst), "l"(src) : "memory")
#define CP_COMMIT() asm volatile("cp.async.commit_group;" ::: "memory")
#define CP_WAIT1()  asm volatile("cp.async.wait_group 1;" ::: "memory")
#define CP_WAIT0()  asm volatile("cp.async.wait_group 0;" ::: "memory")

#define LDSM_X4(r0, r1, r2, r3, addr) \
    asm volatile("ldmatrix.sync.aligned.m8n8.x4.shared.b16 {%0,%1,%2,%3}, [%4];" \
                 : "=r"(r0), "=r"(r1), "=r"(r2), "=r"(r3) : "r"(addr))

__device__ __forceinline__ void mma_f16(float* c, uint32_t a0, uint32_t a1,
                                        uint32_t a2, uint32_t a3,
                                        uint32_t b0, uint32_t b1) {
    asm volatile(
        "mma.sync.aligned.m16n8k16.row.col.f32.f16.f16.f32 "
        "{%0,%1,%2,%3}, {%4,%5,%6,%7}, {%8,%9}, {%0,%1,%2,%3};"
        : "+f"(c[0]), "+f"(c[1]), "+f"(c[2]), "+f"(c[3])
        : "r"(a0), "r"(a1), "r"(a2), "r"(a3), "r"(b0), "r"(b1));
}

// ===================== misc helpers ========================================
__device__ __forceinline__ unsigned f2key(float f) {
    unsigned u = __float_as_uint(f);
    return (u & 0x80000000u) ? ~u : (u | 0x80000000u);
}
__device__ __forceinline__ float key2f(unsigned k) {
    unsigned u = (k & 0x80000000u) ? (k ^ 0x80000000u) : ~k;
    return __uint_as_float(u);
}
enum { ACT_NONE = 0, ACT_RELU = 1, ACT_SIG = 2 };
__device__ __forceinline__ float apply_act(float v, int act) {
    if (act == ACT_RELU) return fmaxf(v, 0.0f);
    if (act == ACT_SIG)  return 1.0f / (1.0f + expf(-v));
    return v;
}

// ===================== fp32 -> fp16 conversion =============================
__global__ void __launch_bounds__(256)
conv_h(const float* __restrict__ in, hf* __restrict__ outp, int n)
{
    int i = (blockIdx.x * 256 + threadIdx.x) * 4;
    if (i >= n) return;
    float4 v = *(const float4*)(in + i);
    __half2 a = __floats2half2_rn(v.x, v.y);
    __half2 b = __floats2half2_rn(v.z, v.w);
    uint2 p;
    p.x = *(uint32_t*)&a; p.y = *(uint32_t*)&b;
    *(uint2*)(outp + i) = p;
}

// ===================== fp16 warp-MMA GEMM ==================================
// C = act(A[M,K] @ B[N,K]^T + bias); A,B fp16, fp32 accumulate.
// BM=BN=128, BK=64. 16 warps (4x4), warp tile 32x32. 3-stage cp.async.
#define ROW_BYTES   144u
#define TIER_BYTES  18432u           // 128 * 144
#define NSTAGE      3
#define GSMEM2      (NSTAGE * 2 * 18432 + 1024)

template <int ACT, bool OUTF>
__global__ void __launch_bounds__(512, 1)
gemm_mma(const hf* __restrict__ A, const hf* __restrict__ Bm,
         const float* __restrict__ bias,
         float* __restrict__ Cf, hf* __restrict__ Ch,
         int M, int N, int K)
{
    constexpr uint32_t STB = 2 * TIER_BYTES;
    extern __shared__ char smem[];
    const uint32_t sb = smem_to_u32(smem);
    const int tid = threadIdx.x;
    const int wid = tid >> 5, lane = tid & 31;
    const int wm = wid & 3, wn = wid >> 2;
    const int bm = blockIdx.y * 128, bn = blockIdx.x * 128;

    float* biasS = (float*)(smem + NSTAGE * STB);
    if (!OUTF && tid < 128) biasS[tid] = bias[bn + tid];

    const int quad = lane >> 3, r8 = lane & 7;
    const uint32_t aoff = (uint32_t)((wm * 32 + (quad & 1) * 8 + r8) * ROW_BYTES
                                     + (quad >> 1) * 16);
    const uint32_t boff = (uint32_t)((wn * 32 + (quad >> 1) * 8 + r8) * ROW_BYTES
                                     + (quad & 1) * 16);

    float acc[2][4][4];
#pragma unroll
    for (int i = 0; i < 2; i++)
#pragma unroll
        for (int j = 0; j < 4; j++)
#pragma unroll
            for (int q = 0; q < 4; q++) acc[i][j][q] = 0.0f;

    const int T = K >> 6;

    auto load_stage = [&](int st, int k0) {
        const uint32_t base = sb + (uint32_t)st * STB;
#pragma unroll
        for (int i = 0; i < 4; i++) {
            int id = tid + i * 512;              // 0..2047
            int tier = id >> 10;
            int rid = id & 1023;
            int row = rid >> 3, c = rid & 7;
            const hf* src = (tier == 0) ? A : Bm;
            int rbase = (tier == 0) ? bm : bn;
            const hf* g = src + (size_t)(rbase + row) * K + k0 + c * 8;
            uint32_t d = base + (uint32_t)tier * TIER_BYTES
                         + (uint32_t)row * ROW_BYTES + (uint32_t)c * 16;
            CP_ASYNC16(d, g);
        }
        CP_COMMIT();
    };

    auto compute_stage = [&](int st) {
        const uint32_t base = sb + (uint32_t)st * STB;
        const uint32_t Ah = base;
        const uint32_t Bh = base + TIER_BYTES;
#pragma unroll
        for (int ks = 0; ks < 4; ks++) {
            const uint32_t ko = (uint32_t)ks * 32;
            uint32_t ah[2][4], bh[2][4];
            LDSM_X4(ah[0][0], ah[0][1], ah[0][2], ah[0][3], Ah + aoff + ko);
            LDSM_X4(ah[1][0], ah[1][1], ah[1][2], ah[1][3], Ah + aoff + 2304 + ko);
            LDSM_X4(bh[0][0], bh[0][1], bh[0][2], bh[0][3], Bh + boff + ko);
            LDSM_X4(bh[1][0], bh[1][1], bh[1][2], bh[1][3], Bh + boff + 2304 + ko);
#pragma unroll
            for (int p = 0; p < 2; p++)
#pragma unroll
                for (int sub = 0; sub < 2; sub++) {
                    int nj = p * 2 + sub;
                    uint32_t h0 = bh[p][sub * 2], h1 = bh[p][sub * 2 + 1];
#pragma unroll
                    for (int mi = 0; mi < 2; mi++)
                        mma_f16(acc[mi][nj], ah[mi][0], ah[mi][1], ah[mi][2], ah[mi][3], h0, h1);
                }
        }
    };

    load_stage(0, 0);
    load_stage(1, 64);
    for (int t = 0; t < T; t++) {
        if (t + 1 < T) CP_WAIT1(); else CP_WAIT0();
        __syncthreads();
        if (t + 2 < T) load_stage((t + 2) % NSTAGE, (t + 2) * 64);
        compute_stage(t % NSTAGE);
    }

    // ---------------- epilogue ----------------
    float lmin = INFINITY, lmax = -INFINITY;
    const int rbase = bm + wm * 32 + (lane >> 2);
    const int cloc0 = wn * 32 + (lane & 3) * 2;
#pragma unroll
    for (int mi = 0; mi < 2; mi++) {
#pragma unroll
        for (int nj = 0; nj < 4; nj++) {
            int cl = cloc0 + nj * 8;
            int n0 = bn + cl;
            float b0 = 0.f, b1 = 0.f;
            if (!OUTF) { b0 = biasS[cl]; b1 = biasS[cl + 1]; }
#pragma unroll
            for (int h = 0; h < 2; h++) {
                int m = rbase + mi * 16 + h * 8;
                float v0 = apply_act(acc[mi][nj][h * 2 + 0] + b0, ACT);
                float v1 = apply_act(acc[mi][nj][h * 2 + 1] + b1, ACT);
                if (OUTF) {
                    lmin = fminf(lmin, fminf(v0, v1));
                    lmax = fmaxf(lmax, fmaxf(v0, v1));
                    *(float2*)(Cf + (size_t)m * N + n0) = make_float2(v0, v1);
                } else {
                    __half2 hv = __floats2half2_rn(v0, v1);
                    *(__half2*)(Ch + (size_t)m * N + n0) = hv;
                }
            }
        }
    }

    if (OUTF) {
        float* red = (float*)smem;
        __syncthreads();
        red[tid] = lmin; red[512 + tid] = lmax;
        __syncthreads();
#pragma unroll
        for (int s = 256; s >= 64; s >>= 1) {
            if (tid < s) {
                red[tid] = fminf(red[tid], red[tid + s]);
                red[512 + tid] = fmaxf(red[512 + tid], red[512 + tid + s]);
            }
            __syncthreads();
        }
        if (tid < 32) {
            float a = fminf(red[tid], red[tid + 32]);
            float b = fmaxf(red[512 + tid], red[512 + tid + 32]);
#pragma unroll
            for (int o = 16; o > 0; o >>= 1) {
                a = fminf(a, __shfl_down_sync(0xffffffffu, a, o));
                b = fmaxf(b, __shfl_down_sync(0xffffffffu, b, o));
            }
            if (tid == 0) {
                atomicMin(&g_minkey, f2key(a));
                atomicMax(&g_maxkey, f2key(b));
            }
        }
    }
}

// ===================== N=1 projection from fp16 activations ================
template <int ACT>
__global__ void __launch_bounds__(256)
rowdot_h(const hf* __restrict__ act, const float* __restrict__ w,
         const float* __restrict__ bias, float* __restrict__ out, int K)
{
    const int warp = threadIdx.x >> 5, lane = threadIdx.x & 31;
    const int row = blockIdx.x * 8 + warp;
    const hf* a = act + (size_t)row * K;
    float s = 0.0f;
    for (int k = lane * 8; k < K; k += 32 * 8) {
        uint4 av = *(const uint4*)(a + k);
        float4 w0 = *(const float4*)(w + k);
        float4 w1 = *(const float4*)(w + k + 4);
        const uint32_t au[4] = {av.x, av.y, av.z, av.w};
        const float wf[8] = {w0.x, w0.y, w0.z, w0.w, w1.x, w1.y, w1.z, w1.w};
#pragma unroll
        for (int q = 0; q < 4; q++) {
            __half2 h2 = *(const __half2*)&au[q];
            s += __low2float(h2) * wf[q * 2];
            s += __high2float(h2) * wf[q * 2 + 1];
        }
    }
#pragma unroll
    for (int o = 16; o > 0; o >>= 1) s += __shfl_down_sync(0xffffffffu, s, o);
    if (lane == 0) out[row] = apply_act(s + bias[0], ACT);
}

// ===================== min/max init + final rescale ========================
__global__ void init_minmax_k() { g_minkey = 0xFFFFFFFFu; g_maxkey = 0u; }

__global__ void __launch_bounds__(256)
scale_out(const float* __restrict__ s, float* __restrict__ out)
{
    float mn = key2f(g_minkey);
    float mx = key2f(g_maxkey);
    float inv = 1.0f / (mx - mn);
    size_t i = ((size_t)blockIdx.x * blockDim.x + threadIdx.x) * 8;
#pragma unroll
    for (int j = 0; j < 2; j++) {
        float4 v = *(const float4*)&s[i + j * 4];
        float4 o;
        o.x = (v.x - mn) * inv; o.y = (v.y - mn) * inv;
        o.z = (v.z - mn) * inv; o.w = (v.w - mn) * inv;
        *(float4*)&out[i + j * 4] = o;
    }
}

// ===================== host launch =========================================
static void launch_layer(cudaStream_t st, int act, const hf* A, const hf* W,
                         const float* bias, hf* C, int M, int N, int K)
{
    dim3 grid(N / 128, M / 128), blk(512);
    if (act == ACT_RELU) {
        cudaFuncSetAttribute(gemm_mma<ACT_RELU, false>,
                             cudaFuncAttributeMaxDynamicSharedMemorySize, GSMEM2);
        gemm_mma<ACT_RELU, false><<<grid, blk, GSMEM2, st>>>(
            A, W, bias, nullptr, C, M, N, K);
    } else {
        cudaFuncSetAttribute(gemm_mma<ACT_SIG, false>,
                             cudaFuncAttributeMaxDynamicSharedMemorySize, GSMEM2);
        gemm_mma<ACT_SIG, false><<<grid, blk, GSMEM2, st>>>(
            A, W, bias, nullptr, C, M, N, K);
    }
}

extern "C" void kernel_launch(void* const* d_in, const int* in_sizes, int n_in,
                              void* d_out, int out_size)
{
    (void)in_sizes; (void)n_in; (void)out_size;
    const float* x1   = (const float*)d_in[0];
    const float* x2   = (const float*)d_in[1];
    const float* W1_1 = (const float*)d_in[2];   const float* b1_1 = (const float*)d_in[3];
    const float* W1_2 = (const float*)d_in[4];   const float* b1_2 = (const float*)d_in[5];
    const float* W1_3 = (const float*)d_in[6];   const float* b1_3 = (const float*)d_in[7];
    const float* W1_4 = (const float*)d_in[8];   const float* b1_4 = (const float*)d_in[9];
    const float* W1_5 = (const float*)d_in[10];  const float* b1_5 = (const float*)d_in[11];
    const float* Wp1  = (const float*)d_in[12];  const float* bp1  = (const float*)d_in[13];
    const float* W2_1 = (const float*)d_in[14];  const float* b2_1 = (const float*)d_in[15];
    const float* W2_2 = (const float*)d_in[16];  const float* b2_2 = (const float*)d_in[17];
    const float* W2_3 = (const float*)d_in[18];  const float* b2_3 = (const float*)d_in[19];
    const float* Wp2  = (const float*)d_in[20];  const float* bp2  = (const float*)d_in[21];

    float* out = (float*)d_out;
    const int B = 4096;
    const int H = 2048;                  // row-group size (B/2)
    const size_t NSC = (size_t)4096 * 4096;

    hf *actA, *actB, *actD, *actC, *x1v, *x2v, *wh, *inp;
    float* scores;
    cudaGetSymbolAddress((void**)&actA, g_actA);
    cudaGetSymbolAddress((void**)&actB, g_actB);
    cudaGetSymbolAddress((void**)&actD, g_actD);
    cudaGetSymbolAddress((void**)&actC, g_actC);
    cudaGetSymbolAddress((void**)&x1v, g_x1v);
    cudaGetSymbolAddress((void**)&x2v, g_x2v);
    cudaGetSymbolAddress((void**)&wh, g_wh);
    cudaGetSymbolAddress((void**)&inp, g_in);
    cudaGetSymbolAddress((void**)&scores, g_scores);

    // streams/events created once (host-side only; no device allocation)
    // Exactly 4 streams (0, s2, s3, s4) — 5 streams trips the teardown check.
    static cudaStream_t s2 = nullptr, s3 = nullptr, s4 = nullptr;
    static cudaEvent_t evFork = nullptr, evX1v0 = nullptr, evX1v1 = nullptr,
                       evX2v = nullptr, evB2 = nullptr, evS3 = nullptr,
                       evW1r = nullptr, evW11 = nullptr, evX1c = nullptr,
                       evG1 = nullptr;
    if (!s2) {
        cudaStreamCreateWithFlags(&s2, cudaStreamNonBlocking);
        cudaStreamCreateWithFlags(&s3, cudaStreamNonBlocking);
        cudaStreamCreateWithFlags(&s4, cudaStreamNonBlocking);
        cudaEventCreateWithFlags(&evFork, cudaEventDisableTiming);
        cudaEventCreateWithFlags(&evX1v0, cudaEventDisableTiming);
        cudaEventCreateWithFlags(&evX1v1, cudaEventDisableTiming);
        cudaEventCreateWithFlags(&evX2v,  cudaEventDisableTiming);
        cudaEventCreateWithFlags(&evB2,   cudaEventDisableTiming);
        cudaEventCreateWithFlags(&evS3,   cudaEventDisableTiming);
        cudaEventCreateWithFlags(&evW1r,  cudaEventDisableTiming);
        cudaEventCreateWithFlags(&evW11,  cudaEventDisableTiming);
        cudaEventCreateWithFlags(&evX1c,  cudaEventDisableTiming);
        cudaEventCreateWithFlags(&evG1,   cudaEventDisableTiming);
    }

    // ---- stream0: init + fork ----
    init_minmax_k<<<1, 1>>>();
    cudaEventRecord(evFork, 0);
    cudaStreamWaitEvent(s2, evFork, 0);
    cudaStreamWaitEvent(s4, evFork, 0);

    // ---- s4: W1 weight convs, then branch-1 row-group 1 pipeline ----
    conv_h<<<2097152 / 1024, 256, 0, s4>>>(W1_1, wh + OW11, 2097152);
    cudaEventRecord(evW11, s4);
    conv_h<<<2097152 / 1024, 256, 0, s4>>>(W1_2, wh + OW12, 2097152);
    conv_h<<<524288 / 1024, 256, 0, s4>>>(W1_3, wh + OW13, 524288);
    conv_h<<<524288 / 1024, 256, 0, s4>>>(W1_4, wh + OW14, 524288);
    conv_h<<<2097152 / 1024, 256, 0, s4>>>(W1_5, wh + OW15, 2097152);
    cudaEventRecord(evW1r, s4);

    // ---- s2: branch 2 (independent of branch 1) ----
    conv_h<<<2097152 / 1024, 256, 0, s2>>>(x2, inp + OX2, 2097152);
    conv_h<<<524288 / 1024, 256, 0, s2>>>(W2_1, wh + OW21, 524288);
    conv_h<<<524288 / 1024, 256, 0, s2>>>(W2_2, wh + OW22, 524288);
    conv_h<<<524288 / 1024, 256, 0, s2>>>(W2_3, wh + OW23, 524288);
    launch_layer(s2, ACT_RELU, inp + OX2, wh + OW21, b2_1, actC, B, 1024, 512);
    launch_layer(s2, ACT_SIG,  actC, wh + OW22, b2_2, x2v, B, 512, 1024);
    cudaEventRecord(evX2v, s2);
    launch_layer(s2, ACT_RELU, x2v, wh + OW23, b2_3, actC, B, 1024, 512);
    rowdot_h<ACT_SIG><<<B / 8, 256, 0, s2>>>(actC, Wp2, bp2, out + 4096 + NSC, 1024); // pre_model
    cudaEventRecord(evB2, s2);

    // ---- stream0: x1 conversion (parallel with W1 convs on s4) ----
    conv_h<<<4194304 / 1024, 256>>>(x1, inp + OX1, 4194304);
    cudaEventRecord(evX1c, 0);

    // ---- branch 1 as two independent 2048-row pipelines ----
    // group 0 on stream0, group 1 on s4 (after its weight convs).
    // Disjoint buffer regions per group:
    //   L1 out: actA + g*H*2048   L2 out: actB + g*H*1024
    //   L3 out: x1v + g*H*512     L4 out: actD + g*H*1024
    //   L5 out: actA + g*H*2048 (reuse own L1 region; own L2 already consumed)
    cudaStreamWaitEvent(0, evW11, 0);
    cudaStreamWaitEvent(s4, evX1c, 0);

    for (int g = 0; g < 2; g++) {
        cudaStream_t sg = (g == 0) ? (cudaStream_t)0 : s4;
        const hf* xin = inp + OX1 + (size_t)g * H * 1024;
        hf* a1 = actA + (size_t)g * H * 2048;
        hf* a2 = actB + (size_t)g * H * 1024;
        hf* xv = x1v  + (size_t)g * H * 512;
        hf* a4 = actD + (size_t)g * H * 1024;
        hf* a5 = actA + (size_t)g * H * 2048;

        launch_layer(sg, ACT_RELU, xin, wh + OW11, b1_1, a1, H, 2048, 1024);
        if (g == 0) cudaStreamWaitEvent(sg, evW1r, 0);   // s4 has them in-stream
        launch_layer(sg, ACT_RELU, a1, wh + OW12, b1_2, a2, H, 1024, 2048);
        launch_layer(sg, ACT_SIG,  a2, wh + OW13, b1_3, xv, H, 512, 1024);
        cudaEventRecord(g == 0 ? evX1v0 : evX1v1, sg);
        launch_layer(sg, ACT_RELU, xv, wh + OW14, b1_4, a4, H, 1024, 512);
        launch_layer(sg, ACT_RELU, a4, wh + OW15, b1_5, a5, H, 2048, 1024);
        rowdot_h<ACT_SIG><<<H / 8, 256, 0, sg>>>(a5, Wp1, bp1,
                                                 out + (size_t)g * H, 2048); // pre_data
    }
    cudaEventRecord(evG1, s4);

    // ---- s3: cross scores (two M-halves) + rescale ----
    cudaStreamWaitEvent(s3, evX2v, 0);
    cudaFuncSetAttribute(gemm_mma<ACT_NONE, true>,
                         cudaFuncAttributeMaxDynamicSharedMemorySize, GSMEM2);
    for (int g = 0; g < 2; g++) {
        cudaStreamWaitEvent(s3, g == 0 ? evX1v0 : evX1v1, 0);
        dim3 grid(4096 / 128, H / 128), blk(512);
        gemm_mma<ACT_NONE, true><<<grid, blk, GSMEM2, s3>>>(
            x1v + (size_t)g * H * 512, x2v, nullptr,
            scores + (size_t)g * H * 4096, nullptr, H, 4096, 512);
    }
    scale_out<<<(unsigned)(NSC / 8 / 256), 256, 0, s3>>>(scores, out + 4096);     // pre_dm
    cudaEventRecord(evS3, s3);

    // ---- join everything back into stream0 ----
    cudaStreamWaitEvent(0, evB2, 0);
    cudaStreamWaitEvent(0, evS3, 0);
    cudaStreamWaitEvent(0, evG1, 0);
}